// round 3
// baseline (speedup 1.0000x reference)
#include <cuda_runtime.h>
#include <cstdint>

// GridSample1d: N=64, C=64, L_in=4096, L_out=8192, fp32,
// align_corners=True, padding=border.
//
// R3: VEC=4 (8 independent LDS.128 in flight/thread), STG.128 outputs,
// streaming cache hints (.cs) on input stage + output, grid prefetch.
// Keeps R2's channel-interleaved swizzled SMEM layout (1 LDS.128 = 1 tap
// x 4 channels).

#define N_B     64
#define C_TOT   64
#define L_IN    4096
#define L_OUT   8192
#define CG      4          // channels per block (packed in one float4)
#define THREADS 512
#define VEC     4          // l_out positions per thread per iteration
#define ITERS   (L_OUT / (THREADS * VEC))   // 4

__device__ __forceinline__ uint32_t swz(uint32_t byte_off) {
    return byte_off ^ ((byte_off >> 3) & 0x70);
}

__global__ __launch_bounds__(THREADS)
void gs1d_kernel(const float* __restrict__ inp,
                 const float* __restrict__ grid,
                 float* __restrict__ out)
{
    extern __shared__ char s_raw[];   // 4096 float4 = 64 KB, swizzled

    const int blk = blockIdx.x;
    const int n  = blk / (C_TOT / CG);
    const int cg = blk % (C_TOT / CG);
    const int c0 = cg * CG;

    // ---- stage: transpose [CG][L_IN] -> interleaved float4[L_IN], swizzled ----
    {
        const float* base = inp + ((size_t)n * C_TOT + c0) * L_IN;
        for (int i0 = threadIdx.x * 4; i0 < L_IN; i0 += THREADS * 4) {
            float4 a[CG];
            #pragma unroll
            for (int c = 0; c < CG; ++c)
                a[c] = __ldcs(reinterpret_cast<const float4*>(
                           base + (size_t)c * L_IN + i0));
            #pragma unroll
            for (int k = 0; k < 4; ++k) {
                float4 v;
                v.x = ((const float*)&a[0])[k];
                v.y = ((const float*)&a[1])[k];
                v.z = ((const float*)&a[2])[k];
                v.w = ((const float*)&a[3])[k];
                *reinterpret_cast<float4*>(s_raw + swz((uint32_t)(i0 + k) * 16u)) = v;
            }
        }
    }
    __syncthreads();

    const float* grow  = grid + (size_t)n * L_OUT;
    float*       obase = out  + ((size_t)n * C_TOT + c0) * L_OUT;

    const float scale = 0.5f * (float)(L_IN - 1);

    // prefetch first grid vector
    float4 g = __ldg(reinterpret_cast<const float4*>(grow + threadIdx.x * VEC));

    #pragma unroll
    for (int it = 0; it < ITERS; ++it) {
        const int l0 = it * (THREADS * VEC) + threadIdx.x * VEC;

        const float xs[VEC] = {g.x, g.y, g.z, g.w};

        // prefetch next iteration's grid vector
        if (it + 1 < ITERS)
            g = __ldg(reinterpret_cast<const float4*>(
                    grow + l0 + THREADS * VEC));

        float r[CG][VEC];

        #pragma unroll
        for (int j = 0; j < VEC; ++j) {
            float x = (xs[j] + 1.0f) * scale;               // align_corners
            x = fminf(fmaxf(x, 0.0f), (float)(L_IN - 1));   // border clamp
            float xf = floorf(x);
            int   i0 = (int)xf;
            float w1 = x - xf;
            float w0 = 1.0f - w1;
            int   i1 = min(i0 + 1, L_IN - 1);

            const float4 v0 = *reinterpret_cast<const float4*>(
                s_raw + swz((uint32_t)i0 * 16u));
            const float4 v1 = *reinterpret_cast<const float4*>(
                s_raw + swz((uint32_t)i1 * 16u));

            r[0][j] = w0 * v0.x + w1 * v1.x;
            r[1][j] = w0 * v0.y + w1 * v1.y;
            r[2][j] = w0 * v0.z + w1 * v1.z;
            r[3][j] = w0 * v0.w + w1 * v1.w;
        }

        #pragma unroll
        for (int c = 0; c < CG; ++c) {
            float4 o = make_float4(r[c][0], r[c][1], r[c][2], r[c][3]);
            __stcs(reinterpret_cast<float4*>(obase + (size_t)c * L_OUT + l0), o);
        }
    }
}

extern "C" void kernel_launch(void* const* d_in, const int* in_sizes, int n_in,
                              void* d_out, int out_size)
{
    const float* inp  = (const float*)d_in[0];  // [64, 64, 4096]
    const float* grid = (const float*)d_in[1];  // [64, 8192]
    float*       out  = (float*)d_out;          // [64, 64, 8192]

    const int smem_bytes = L_IN * (int)sizeof(float4);  // 64 KB
    cudaFuncSetAttribute(gs1d_kernel,
                         cudaFuncAttributeMaxDynamicSharedMemorySize,
                         smem_bytes);

    const int blocks = N_B * (C_TOT / CG);  // 1024
    gs1d_kernel<<<blocks, THREADS, smem_bytes>>>(inp, grid, out);
}